// round 6
// baseline (speedup 1.0000x reference)
#include <cuda_runtime.h>

#define N_NODES 50000
#define N_EDGES 800000
#define NODE_DIM 64
#define HIDDEN 128
#define OUT_DIM 256
#define N_LAYERS 3
#define GRID_BLOCKS 148
#define CSR_THREADS 256

typedef unsigned long long u64;

// Scratch (static device globals; no runtime allocation)
__device__ float d_hbuf0[(size_t)N_NODES * HIDDEN];
__device__ float d_hbuf1[(size_t)N_NODES * HIDDEN];
__device__ float d_deg[N_NODES];      // 1/deg (0 for isolated nodes)
__device__ float d_gsum[HIDDEN];
__device__ int   d_cnt[N_NODES];      // histogram
__device__ int   d_row[N_NODES + 1];  // CSR row offsets
__device__ int   d_cur[N_NODES];      // fill cursors
__device__ int   d_colA[N_EDGES];     // CSR column (src node per edge slot)
__device__ int   d_bsum[GRID_BLOCKS];
__device__ unsigned int g_count;      // global barrier arrive counter (zero-init)
__device__ unsigned int g_sense;      // global barrier sense (zero-init; even flips/launch)

// ---- packed f32x2 helpers (Blackwell dual-FMA) -----------------------------
__device__ __forceinline__ u64 pack2(float lo, float hi) {
    u64 r;
    asm("mov.b64 %0, {%1, %2};" : "=l"(r)
        : "r"(__float_as_uint(lo)), "r"(__float_as_uint(hi)));
    return r;
}
__device__ __forceinline__ void unpack2(u64 v, float& lo, float& hi) {
    unsigned int a, b;
    asm("mov.b64 {%0, %1}, %2;" : "=r"(a), "=r"(b) : "l"(v));
    lo = __uint_as_float(a);
    hi = __uint_as_float(b);
}
__device__ __forceinline__ void fma2(u64& acc, u64 a, u64 b) {
    asm("fma.rn.f32x2 %0, %1, %2, %0;" : "+l"(acc) : "l"(a), "l"(b));
}

// ---- sense-reversing grid barrier (all GRID_BLOCKS resident) ---------------
__device__ __forceinline__ void gbar(unsigned int& sense) {
    __syncthreads();
    if (threadIdx.x == 0) {
        __threadfence();
        unsigned int old = atomicAdd(&g_count, 1);
        if (old == GRID_BLOCKS - 1) {
            g_count = 0;                 // exclusive: all blocks have arrived
            __threadfence();
            g_sense = sense ^ 1;         // release
        } else {
            while (*(volatile unsigned int*)&g_sense == sense) { }
        }
        __threadfence();                 // acquire
    }
    sense ^= 1;
    __syncthreads();
}

// ---------------------------------------------------------------------------
// Single-kernel CSR build: zero -> hist -> scan -> cur/deg -> fill
__global__ void __launch_bounds__(CSR_THREADS) csr_kernel(const int* __restrict__ src,
                                                          const int* __restrict__ dst) {
    unsigned int sense = 0;   // g_sense is always 0 at kernel entry (even # flips)
    const int gt = blockIdx.x * CSR_THREADS + threadIdx.x;
    const int nthreads = GRID_BLOCKS * CSR_THREADS;   // 37888

    // Phase A: zero cnt + gsum
    for (int i = gt; i < N_NODES; i += nthreads) d_cnt[i] = 0;
    if (gt < HIDDEN) d_gsum[gt] = 0.0f;
    gbar(sense);

    // Phase B: degree histogram
    for (int e = gt; e < N_EDGES; e += nthreads) atomicAdd(&d_cnt[dst[e]], 1);
    gbar(sense);

    // Phase C: scan. Thread g owns elements 2g, 2g+1 (37888*2 >= 50000).
    int i0 = 2 * gt, i1 = 2 * gt + 1;
    int c0 = (i0 < N_NODES) ? d_cnt[i0] : 0;
    int c1 = (i1 < N_NODES) ? d_cnt[i1] : 0;
    int s = c0 + c1;
    int lane = threadIdx.x & 31;
    int wid = threadIdx.x >> 5;
    int incl = s;
#pragma unroll
    for (int off = 1; off < 32; off <<= 1) {
        int v = __shfl_up_sync(0xffffffffu, incl, off);
        if (lane >= off) incl += v;
    }
    __shared__ int wsum[8];
    __shared__ int wpre[8];
    if (lane == 31) wsum[wid] = incl;
    __syncthreads();
    if (threadIdx.x == 0) {
        int acc = 0;
#pragma unroll
        for (int j = 0; j < 8; j++) { wpre[j] = acc; acc += wsum[j]; }
        d_bsum[blockIdx.x] = acc;
    }
    __syncthreads();
    int texcl = wpre[wid] + incl - s;   // exclusive prefix within block
    gbar(sense);

    // Phase D: block prefix + write row/cur/deg
    __shared__ int s_bpre;
    if (threadIdx.x == 0) {
        int acc = 0;
        for (int j = 0; j < (int)blockIdx.x; j++) acc += d_bsum[j];
        s_bpre = acc;
    }
    __syncthreads();
    int base = s_bpre + texcl;
    if (i0 < N_NODES) {
        d_row[i0] = base; d_cur[i0] = base;
        d_deg[i0] = c0 ? (1.0f / (float)c0) : 0.0f;
    }
    if (i1 < N_NODES) {
        d_row[i1] = base + c0; d_cur[i1] = base + c0;
        d_deg[i1] = c1 ? (1.0f / (float)c1) : 0.0f;
    }
    if (gt == 0) d_row[N_NODES] = N_EDGES;
    gbar(sense);

    // Phase E: fill CSR columns
    for (int e = gt; e < N_EDGES; e += nthreads) {
        int d = dst[e];
        int pos = atomicAdd(&d_cur[d], 1);
        d_colA[pos] = src[e];
    }
}

// ---------------------------------------------------------------------------
// h0 = x @ Wp + bp   (x: [N,64], Wp: [64,128]) -> d_hbuf0
// 128 threads, 32 nodes; thread (nt,ct) owns 8 nodes x 4 cols.
__global__ void __launch_bounds__(128) proj_kernel(const float* __restrict__ x,
                            const float* __restrict__ Wp,
                            const float* __restrict__ bp) {
    __shared__ float xs[32][NODE_DIM];
    int t = threadIdx.x;
    int node0 = blockIdx.x * 32;

    for (int i = t; i < 32 * (NODE_DIM / 4); i += 128) {
        int r = i >> 4;
        int c4 = i & 15;
        int node = node0 + r;
        float4 v = make_float4(0.f, 0.f, 0.f, 0.f);
        if (node < N_NODES)
            v = ((const float4*)(x + (size_t)node * NODE_DIM))[c4];
        *(float4*)&xs[r][c4 * 4] = v;
    }
    __syncthreads();

    int ct = t & 31;
    int nt = t >> 5;
    int colb = ct * 4;

    u64 acc2[8][2];
#pragma unroll
    for (int i = 0; i < 8; i++) { acc2[i][0] = 0ull; acc2[i][1] = 0ull; }

    const float4* W4 = (const float4*)Wp;
#pragma unroll 4
    for (int k = 0; k < NODE_DIM; k++) {
        float4 w = W4[k * 32 + ct];
        u64 wp0 = pack2(w.x, w.y);
        u64 wp1 = pack2(w.z, w.w);
#pragma unroll
        for (int i = 0; i < 8; i++) {
            float m = xs[nt * 8 + i][k];
            u64 mp = pack2(m, m);
            fma2(acc2[i][0], mp, wp0);
            fma2(acc2[i][1], mp, wp1);
        }
    }

    float4 bv = ((const float4*)bp)[ct];
#pragma unroll
    for (int i = 0; i < 8; i++) {
        int node = node0 + nt * 8 + i;
        if (node < N_NODES) {
            float4 r;
            unpack2(acc2[i][0], r.x, r.y);
            unpack2(acc2[i][1], r.z, r.w);
            r.x += bv.x; r.y += bv.y; r.z += bv.z; r.w += bv.w;
            *(float4*)(d_hbuf0 + (size_t)node * HIDDEN + colb) = r;
        }
    }
}

// ---------------------------------------------------------------------------
// Fused GNN layer: hout = relu(hin + (gather_mean(hin) @ Wg) + bg)
// Gather: warp w owns nodes w*8..w*8+7; TWO nodes' edge lists interleaved,
// unroll-4 each. GEMM: thread owns 8 nodes x 4 cols, packed fma2.
// do_reduce: also accumulate column sums of hout into d_gsum (last layer).
__global__ void __launch_bounds__(128) layer_kernel(const float* __restrict__ hin,
                             float* __restrict__ hout,
                             const float* __restrict__ Wg,
                             const float* __restrict__ bg,
                             int do_reduce) {
    __shared__ float ms[32][HIDDEN];
    int t = threadIdx.x;
    int node0 = blockIdx.x * 32;
    int lane = t & 31;
    int w = t >> 5;   // warp 0..3

#pragma unroll 1
    for (int ii = 0; ii < 8; ii += 2) {
        int nlA = w * 8 + ii;
        int nlB = nlA + 1;
        int nA = node0 + nlA;
        int nB = node0 + nlB;

        float4 aA0 = make_float4(0.f, 0.f, 0.f, 0.f), aA1 = aA0;
        float4 aB0 = aA0, aB1 = aA0;

        int jA = 0, eA = 0, jB = 0, eB = 0;
        float invA = 0.0f, invB = 0.0f;
        if (nA < N_NODES) { jA = d_row[nA]; eA = d_row[nA + 1]; invA = d_deg[nA]; }
        if (nB < N_NODES) { jB = d_row[nB]; eB = d_row[nB + 1]; invB = d_deg[nB]; }

#pragma unroll 1
        while (jA + 4 <= eA && jB + 4 <= eB) {
            int sA0 = d_colA[jA],     sA1 = d_colA[jA + 1];
            int sA2 = d_colA[jA + 2], sA3 = d_colA[jA + 3];
            int sB0 = d_colA[jB],     sB1 = d_colA[jB + 1];
            int sB2 = d_colA[jB + 2], sB3 = d_colA[jB + 3];
            float4 vA0 = ((const float4*)(hin + (size_t)sA0 * HIDDEN))[lane];
            float4 vA1 = ((const float4*)(hin + (size_t)sA1 * HIDDEN))[lane];
            float4 vA2 = ((const float4*)(hin + (size_t)sA2 * HIDDEN))[lane];
            float4 vA3 = ((const float4*)(hin + (size_t)sA3 * HIDDEN))[lane];
            float4 vB0 = ((const float4*)(hin + (size_t)sB0 * HIDDEN))[lane];
            float4 vB1 = ((const float4*)(hin + (size_t)sB1 * HIDDEN))[lane];
            float4 vB2 = ((const float4*)(hin + (size_t)sB2 * HIDDEN))[lane];
            float4 vB3 = ((const float4*)(hin + (size_t)sB3 * HIDDEN))[lane];
            aA0.x += vA0.x; aA0.y += vA0.y; aA0.z += vA0.z; aA0.w += vA0.w;
            aA1.x += vA1.x; aA1.y += vA1.y; aA1.z += vA1.z; aA1.w += vA1.w;
            aA0.x += vA2.x; aA0.y += vA2.y; aA0.z += vA2.z; aA0.w += vA2.w;
            aA1.x += vA3.x; aA1.y += vA3.y; aA1.z += vA3.z; aA1.w += vA3.w;
            aB0.x += vB0.x; aB0.y += vB0.y; aB0.z += vB0.z; aB0.w += vB0.w;
            aB1.x += vB1.x; aB1.y += vB1.y; aB1.z += vB1.z; aB1.w += vB1.w;
            aB0.x += vB2.x; aB0.y += vB2.y; aB0.z += vB2.z; aB0.w += vB2.w;
            aB1.x += vB3.x; aB1.y += vB3.y; aB1.z += vB3.z; aB1.w += vB3.w;
            jA += 4; jB += 4;
        }
#pragma unroll 1
        while (jA + 4 <= eA) {
            int s0 = d_colA[jA],     s1 = d_colA[jA + 1];
            int s2 = d_colA[jA + 2], s3 = d_colA[jA + 3];
            float4 v0 = ((const float4*)(hin + (size_t)s0 * HIDDEN))[lane];
            float4 v1 = ((const float4*)(hin + (size_t)s1 * HIDDEN))[lane];
            float4 v2 = ((const float4*)(hin + (size_t)s2 * HIDDEN))[lane];
            float4 v3 = ((const float4*)(hin + (size_t)s3 * HIDDEN))[lane];
            aA0.x += v0.x; aA0.y += v0.y; aA0.z += v0.z; aA0.w += v0.w;
            aA1.x += v1.x; aA1.y += v1.y; aA1.z += v1.z; aA1.w += v1.w;
            aA0.x += v2.x; aA0.y += v2.y; aA0.z += v2.z; aA0.w += v2.w;
            aA1.x += v3.x; aA1.y += v3.y; aA1.z += v3.z; aA1.w += v3.w;
            jA += 4;
        }
#pragma unroll 1
        while (jA < eA) {
            int s = d_colA[jA++];
            float4 v = ((const float4*)(hin + (size_t)s * HIDDEN))[lane];
            aA0.x += v.x; aA0.y += v.y; aA0.z += v.z; aA0.w += v.w;
        }
#pragma unroll 1
        while (jB + 4 <= eB) {
            int s0 = d_colA[jB],     s1 = d_colA[jB + 1];
            int s2 = d_colA[jB + 2], s3 = d_colA[jB + 3];
            float4 v0 = ((const float4*)(hin + (size_t)s0 * HIDDEN))[lane];
            float4 v1 = ((const float4*)(hin + (size_t)s1 * HIDDEN))[lane];
            float4 v2 = ((const float4*)(hin + (size_t)s2 * HIDDEN))[lane];
            float4 v3 = ((const float4*)(hin + (size_t)s3 * HIDDEN))[lane];
            aB0.x += v0.x; aB0.y += v0.y; aB0.z += v0.z; aB0.w += v0.w;
            aB1.x += v1.x; aB1.y += v1.y; aB1.z += v1.z; aB1.w += v1.w;
            aB0.x += v2.x; aB0.y += v2.y; aB0.z += v2.z; aB0.w += v2.w;
            aB1.x += v3.x; aB1.y += v3.y; aB1.z += v3.z; aB1.w += v3.w;
            jB += 4;
        }
#pragma unroll 1
        while (jB < eB) {
            int s = d_colA[jB++];
            float4 v = ((const float4*)(hin + (size_t)s * HIDDEN))[lane];
            aB0.x += v.x; aB0.y += v.y; aB0.z += v.z; aB0.w += v.w;
        }

        float4 rA, rB;
        rA.x = (aA0.x + aA1.x) * invA; rA.y = (aA0.y + aA1.y) * invA;
        rA.z = (aA0.z + aA1.z) * invA; rA.w = (aA0.w + aA1.w) * invA;
        rB.x = (aB0.x + aB1.x) * invB; rB.y = (aB0.y + aB1.y) * invB;
        rB.z = (aB0.z + aB1.z) * invB; rB.w = (aB0.w + aB1.w) * invB;
        *(float4*)&ms[nlA][lane * 4] = rA;
        *(float4*)&ms[nlB][lane * 4] = rB;
    }
    __syncthreads();

    // Phase 2: (ms @ Wg) — thread (nt=w, ct=lane) owns 8 nodes x 4 cols
    int ct = lane;
    int nt = w;
    int colb = ct * 4;

    u64 acc2[8][2];
#pragma unroll
    for (int i = 0; i < 8; i++) { acc2[i][0] = 0ull; acc2[i][1] = 0ull; }

    const float4* W4 = (const float4*)Wg;
#pragma unroll 4
    for (int k = 0; k < HIDDEN; k++) {
        float4 wv = W4[k * 32 + ct];
        u64 wp0 = pack2(wv.x, wv.y);
        u64 wp1 = pack2(wv.z, wv.w);
#pragma unroll
        for (int i = 0; i < 8; i++) {
            float m = ms[nt * 8 + i][k];
            u64 mp = pack2(m, m);
            fma2(acc2[i][0], mp, wp0);
            fma2(acc2[i][1], mp, wp1);
        }
    }

    float4 bv = ((const float4*)bg)[ct];
    float4 cs = make_float4(0.f, 0.f, 0.f, 0.f);   // column partial sums
#pragma unroll
    for (int i = 0; i < 8; i++) {
        int node = node0 + nt * 8 + i;
        if (node < N_NODES) {
            float4 hv = *(const float4*)(hin + (size_t)node * HIDDEN + colb);
            float lo, hi;
            float4 r;
            unpack2(acc2[i][0], lo, hi);
            r.x = fmaxf(hv.x + lo + bv.x, 0.0f);
            r.y = fmaxf(hv.y + hi + bv.y, 0.0f);
            unpack2(acc2[i][1], lo, hi);
            r.z = fmaxf(hv.z + lo + bv.z, 0.0f);
            r.w = fmaxf(hv.w + hi + bv.w, 0.0f);
            *(float4*)(hout + (size_t)node * HIDDEN + colb) = r;
            cs.x += r.x; cs.y += r.y; cs.z += r.z; cs.w += r.w;
        }
    }
    if (do_reduce) {
        atomicAdd(&d_gsum[colb + 0], cs.x);
        atomicAdd(&d_gsum[colb + 1], cs.y);
        atomicAdd(&d_gsum[colb + 2], cs.z);
        atomicAdd(&d_gsum[colb + 3], cs.w);
    }
}

// ---------------------------------------------------------------------------
__global__ void mlp_kernel(const float* __restrict__ W1,
                           const float* __restrict__ b1,
                           const float* __restrict__ W2,
                           const float* __restrict__ b2,
                           float* __restrict__ out) {
    __shared__ float gs[HIDDEN];
    __shared__ float ts[HIDDEN];
    int t = threadIdx.x;  // 256
    if (t < HIDDEN) gs[t] = d_gsum[t] * (1.0f / (float)N_NODES);
    __syncthreads();
    if (t < HIDDEN) {
        float a = b1[t];
#pragma unroll 8
        for (int k = 0; k < HIDDEN; k++) a += gs[k] * W1[k * HIDDEN + t];
        ts[t] = fmaxf(a, 0.0f);
    }
    __syncthreads();
    {
        float a = b2[t];
#pragma unroll 8
        for (int k = 0; k < HIDDEN; k++) a += ts[k] * W2[k * OUT_DIM + t];
        out[t] = a;
    }
}

// ---------------------------------------------------------------------------
extern "C" void kernel_launch(void* const* d_in, const int* in_sizes, int n_in,
                              void* d_out, int out_size) {
    const float* x   = (const float*)d_in[0];
    const int*   src = (const int*)d_in[1];
    const int*   dst = (const int*)d_in[2];
    const float* Wp  = (const float*)d_in[3];
    const float* bp  = (const float*)d_in[4];
    const float* Wg  = (const float*)d_in[5];
    const float* bg  = (const float*)d_in[6];
    const float* W1  = (const float*)d_in[7];
    const float* b1  = (const float*)d_in[8];
    const float* W2  = (const float*)d_in[9];
    const float* b2  = (const float*)d_in[10];
    float* out = (float*)d_out;

    float *h0, *h1;
    cudaGetSymbolAddress((void**)&h0, d_hbuf0);
    cudaGetSymbolAddress((void**)&h1, d_hbuf1);

    // CSR build (single kernel, internal grid barriers)
    csr_kernel<<<GRID_BLOCKS, CSR_THREADS>>>(src, dst);

    // node projection
    proj_kernel<<<(N_NODES + 31) / 32, 128>>>(x, Wp, bp);

    // GNN layers with ping-pong buffers; last layer fuses the column reduce
    const int nblocks = (N_NODES + 31) / 32;
    float* bufs[2] = {h0, h1};
    for (int l = 0; l < N_LAYERS; l++) {
        float* hin  = bufs[l & 1];
        float* hout = bufs[(l + 1) & 1];
        layer_kernel<<<nblocks, 128>>>(hin, hout,
                                       Wg + (size_t)l * HIDDEN * HIDDEN,
                                       bg + (size_t)l * HIDDEN,
                                       (l == N_LAYERS - 1) ? 1 : 0);
    }

    // MLP head
    mlp_kernel<<<1, 256>>>(W1, b1, W2, b2, out);
}

// round 7
// speedup vs baseline: 1.0143x; 1.0143x over previous
#include <cuda_runtime.h>

#define N_NODES 50000
#define N_EDGES 800000
#define NODE_DIM 64
#define HIDDEN 128
#define OUT_DIM 256
#define N_LAYERS 3
#define BUILD_BLOCKS ((N_NODES + 255) / 256)   // 196
#define ECAP 1024

typedef unsigned long long u64;

// Scratch (static device globals; zero-initialized at load; all phases self-restore)
__device__ float d_hbuf0[(size_t)N_NODES * HIDDEN];
__device__ float d_hbuf1[(size_t)N_NODES * HIDDEN];
__device__ float d_deg[N_NODES];      // 1/deg (0 for isolated nodes)
__device__ float d_gsum[HIDDEN];      // zeroed by build_kernel each call
__device__ int   d_cnt[N_NODES];      // histogram; reset to 0 by build_kernel
__device__ int   d_row[N_NODES + 1];  // CSR row offsets
__device__ int   d_cur[N_NODES];      // fill cursors
__device__ int   d_colA[N_EDGES];     // CSR column (src node per edge slot)
__device__ int   d_bsum[BUILD_BLOCKS];
__device__ unsigned int g_count;      // grid barrier counter (returns to 0)
__device__ unsigned int g_sense;      // grid barrier sense (even flips/launch)

// ---- packed f32x2 helpers (Blackwell dual-FMA) -----------------------------
__device__ __forceinline__ u64 pack2(float lo, float hi) {
    u64 r;
    asm("mov.b64 %0, {%1, %2};" : "=l"(r)
        : "r"(__float_as_uint(lo)), "r"(__float_as_uint(hi)));
    return r;
}
__device__ __forceinline__ void unpack2(u64 v, float& lo, float& hi) {
    unsigned int a, b;
    asm("mov.b64 {%0, %1}, %2;" : "=r"(a), "=r"(b) : "l"(v));
    lo = __uint_as_float(a);
    hi = __uint_as_float(b);
}
__device__ __forceinline__ void fma2(u64& acc, u64 a, u64 b) {
    asm("fma.rn.f32x2 %0, %1, %2, %0;" : "+l"(acc) : "l"(a), "l"(b));
}

// ---- sense-reversing grid barrier (BUILD_BLOCKS co-resident) ----------------
__device__ __forceinline__ void gbar(unsigned int& sense) {
    __syncthreads();
    if (threadIdx.x == 0) {
        __threadfence();
        unsigned int old = atomicAdd(&g_count, 1);
        if (old == BUILD_BLOCKS - 1) {
            g_count = 0;
            __threadfence();
            g_sense = sense ^ 1;        // release
        } else {
            while (*(volatile unsigned int*)&g_sense == sense) { }
        }
        __threadfence();
    }
    sense ^= 1;
    __syncthreads();
}

// ---------------------------------------------------------------------------
// Degree histogram (d_cnt starts zero; build_kernel resets it after reading).
__global__ void hist_kernel(const int* __restrict__ dst) {
    int e = blockIdx.x * blockDim.x + threadIdx.x;
    if (e < N_EDGES) atomicAdd(&d_cnt[dst[e]], 1);
}

// ---------------------------------------------------------------------------
// Cooperative scan + fill: row offsets, cursors, 1/deg, cnt reset, gsum reset,
// then CSR column fill. 196 blocks x 256 threads, 2 grid barriers (even).
__global__ void __launch_bounds__(256) build_kernel(const int* __restrict__ src,
                                                    const int* __restrict__ dst) {
    unsigned int sense = 0;
    int t = threadIdx.x;
    int bid = blockIdx.x;
    int i = bid * 256 + t;
    int lane = t & 31;
    int wid = t >> 5;

    // Phase A: block-level exclusive scan of cnt
    int c = (i < N_NODES) ? d_cnt[i] : 0;
    int incl = c;
#pragma unroll
    for (int off = 1; off < 32; off <<= 1) {
        int v = __shfl_up_sync(0xffffffffu, incl, off);
        if (lane >= off) incl += v;
    }
    __shared__ int wsum[8];
    __shared__ int wpre[8];
    if (lane == 31) wsum[wid] = incl;
    __syncthreads();
    if (t == 0) {
        int acc = 0;
#pragma unroll
        for (int j = 0; j < 8; j++) { wpre[j] = acc; acc += wsum[j]; }
        d_bsum[bid] = acc;
    }
    __syncthreads();
    int excl = wpre[wid] + incl - c;
    gbar(sense);

    // Phase B: block prefix (parallel loads into smem, cheap serial smem sum)
    __shared__ int sb[BUILD_BLOCKS];
    if (t < BUILD_BLOCKS) sb[t] = d_bsum[t];
    __syncthreads();
    __shared__ int s_bpre;
    if (t == 0) {
        int acc = 0;
        for (int j = 0; j < bid; j++) acc += sb[j];
        s_bpre = acc;
    }
    __syncthreads();
    int base = s_bpre + excl;
    if (i < N_NODES) {
        d_row[i] = base;
        d_cur[i] = base;
        d_deg[i] = c ? (1.0f / (float)c) : 0.0f;
        d_cnt[i] = 0;                 // self-restore for next replay
    }
    if (i == 0) d_row[N_NODES] = N_EDGES;
    if (i < HIDDEN) d_gsum[i] = 0.0f; // reset before layer-3 accumulates
    gbar(sense);

    // Phase C: fill CSR columns
    const int nth = BUILD_BLOCKS * 256;  // 50176
    for (int e = i; e < N_EDGES; e += nth) {
        int d = dst[e];
        int pos = atomicAdd(&d_cur[d], 1);
        d_colA[pos] = src[e];
    }
}

// ---------------------------------------------------------------------------
// h0 = x @ Wp + bp   (x: [N,64], Wp: [64,128]) -> d_hbuf0
__global__ void __launch_bounds__(128) proj_kernel(const float* __restrict__ x,
                            const float* __restrict__ Wp,
                            const float* __restrict__ bp) {
    __shared__ float xs[32][NODE_DIM];
    int t = threadIdx.x;
    int node0 = blockIdx.x * 32;

    for (int i = t; i < 32 * (NODE_DIM / 4); i += 128) {
        int r = i >> 4;
        int c4 = i & 15;
        int node = node0 + r;
        float4 v = make_float4(0.f, 0.f, 0.f, 0.f);
        if (node < N_NODES)
            v = ((const float4*)(x + (size_t)node * NODE_DIM))[c4];
        *(float4*)&xs[r][c4 * 4] = v;
    }
    __syncthreads();

    int ct = t & 31;
    int nt = t >> 5;
    int colb = ct * 4;

    u64 acc2[8][2];
#pragma unroll
    for (int i = 0; i < 8; i++) { acc2[i][0] = 0ull; acc2[i][1] = 0ull; }

    const float4* W4 = (const float4*)Wp;
#pragma unroll 4
    for (int k = 0; k < NODE_DIM; k++) {
        float4 w = W4[k * 32 + ct];
        u64 wp0 = pack2(w.x, w.y);
        u64 wp1 = pack2(w.z, w.w);
#pragma unroll
        for (int i = 0; i < 8; i++) {
            float m = xs[nt * 8 + i][k];
            u64 mp = pack2(m, m);
            fma2(acc2[i][0], mp, wp0);
            fma2(acc2[i][1], mp, wp1);
        }
    }

    float4 bv = ((const float4*)bp)[ct];
#pragma unroll
    for (int i = 0; i < 8; i++) {
        int node = node0 + nt * 8 + i;
        if (node < N_NODES) {
            float4 r;
            unpack2(acc2[i][0], r.x, r.y);
            unpack2(acc2[i][1], r.z, r.w);
            r.x += bv.x; r.y += bv.y; r.z += bv.z; r.w += bv.w;
            *(float4*)(d_hbuf0 + (size_t)node * HIDDEN + colb) = r;
        }
    }
}

// ---------------------------------------------------------------------------
// Fused GNN layer: hout = relu(hin + (gather_mean(hin) @ Wg) + bg)
// Edge indices for the whole block are prefetched into smem (coalesced),
// removing the idx->row dependent-load chain. Gather keeps 8 row-LDG.128
// in flight per lane. GEMM: thread owns 8 nodes x 4 cols, packed fma2.
__global__ void __launch_bounds__(128) layer_kernel(const float* __restrict__ hin,
                             float* __restrict__ hout,
                             const float* __restrict__ Wg,
                             const float* __restrict__ bg,
                             int do_reduce) {
    __shared__ float ms[32][HIDDEN];   // 16 KB
    __shared__ int sidx[ECAP];         // 4 KB
    __shared__ int srow[33];
    int t = threadIdx.x;
    int node0 = blockIdx.x * 32;
    int lane = t & 31;
    int w = t >> 5;   // warp 0..3

    if (t < 33) srow[t] = d_row[min(node0 + t, N_NODES)];
    __syncthreads();
    int ebase = srow[0];
    int etot = srow[32] - ebase;
    bool insm = (etot <= ECAP);        // mean 512; overflow ~never, but safe
    if (insm) {
        for (int i = t; i < etot; i += 128) sidx[i] = d_colA[ebase + i];
    }
    __syncthreads();

    // Gather: warp w handles nodes w*8..w*8+7; indices from smem.
#pragma unroll 1
    for (int ii = 0; ii < 8; ii++) {
        int nl = w * 8 + ii;
        int node = node0 + nl;
        float4 a0 = make_float4(0.f, 0.f, 0.f, 0.f), a1 = a0;
        if (node < N_NODES) {
            const int* ip;
            int beg, end;
            if (insm) { ip = sidx;   beg = srow[nl] - ebase; end = srow[nl + 1] - ebase; }
            else      { ip = d_colA; beg = srow[nl];         end = srow[nl + 1]; }
            int j = beg;
#pragma unroll 1
            for (; j + 8 <= end; j += 8) {
                int s0 = ip[j],     s1 = ip[j + 1];
                int s2 = ip[j + 2], s3 = ip[j + 3];
                int s4 = ip[j + 4], s5 = ip[j + 5];
                int s6 = ip[j + 6], s7 = ip[j + 7];
                float4 v0 = ((const float4*)(hin + (size_t)s0 * HIDDEN))[lane];
                float4 v1 = ((const float4*)(hin + (size_t)s1 * HIDDEN))[lane];
                float4 v2 = ((const float4*)(hin + (size_t)s2 * HIDDEN))[lane];
                float4 v3 = ((const float4*)(hin + (size_t)s3 * HIDDEN))[lane];
                float4 v4 = ((const float4*)(hin + (size_t)s4 * HIDDEN))[lane];
                float4 v5 = ((const float4*)(hin + (size_t)s5 * HIDDEN))[lane];
                float4 v6 = ((const float4*)(hin + (size_t)s6 * HIDDEN))[lane];
                float4 v7 = ((const float4*)(hin + (size_t)s7 * HIDDEN))[lane];
                a0.x += v0.x; a0.y += v0.y; a0.z += v0.z; a0.w += v0.w;
                a1.x += v1.x; a1.y += v1.y; a1.z += v1.z; a1.w += v1.w;
                a0.x += v2.x; a0.y += v2.y; a0.z += v2.z; a0.w += v2.w;
                a1.x += v3.x; a1.y += v3.y; a1.z += v3.z; a1.w += v3.w;
                a0.x += v4.x; a0.y += v4.y; a0.z += v4.z; a0.w += v4.w;
                a1.x += v5.x; a1.y += v5.y; a1.z += v5.z; a1.w += v5.w;
                a0.x += v6.x; a0.y += v6.y; a0.z += v6.z; a0.w += v6.w;
                a1.x += v7.x; a1.y += v7.y; a1.z += v7.z; a1.w += v7.w;
            }
            if (j + 4 <= end) {
                int s0 = ip[j], s1 = ip[j + 1], s2 = ip[j + 2], s3 = ip[j + 3];
                float4 v0 = ((const float4*)(hin + (size_t)s0 * HIDDEN))[lane];
                float4 v1 = ((const float4*)(hin + (size_t)s1 * HIDDEN))[lane];
                float4 v2 = ((const float4*)(hin + (size_t)s2 * HIDDEN))[lane];
                float4 v3 = ((const float4*)(hin + (size_t)s3 * HIDDEN))[lane];
                a0.x += v0.x; a0.y += v0.y; a0.z += v0.z; a0.w += v0.w;
                a1.x += v1.x; a1.y += v1.y; a1.z += v1.z; a1.w += v1.w;
                a0.x += v2.x; a0.y += v2.y; a0.z += v2.z; a0.w += v2.w;
                a1.x += v3.x; a1.y += v3.y; a1.z += v3.z; a1.w += v3.w;
                j += 4;
            }
            if (j + 2 <= end) {
                int s0 = ip[j], s1 = ip[j + 1];
                float4 v0 = ((const float4*)(hin + (size_t)s0 * HIDDEN))[lane];
                float4 v1 = ((const float4*)(hin + (size_t)s1 * HIDDEN))[lane];
                a0.x += v0.x; a0.y += v0.y; a0.z += v0.z; a0.w += v0.w;
                a1.x += v1.x; a1.y += v1.y; a1.z += v1.z; a1.w += v1.w;
                j += 2;
            }
            if (j < end) {
                int s = ip[j];
                float4 v = ((const float4*)(hin + (size_t)s * HIDDEN))[lane];
                a0.x += v.x; a0.y += v.y; a0.z += v.z; a0.w += v.w;
            }
            float inv = d_deg[node];
            a0.x = (a0.x + a1.x) * inv; a0.y = (a0.y + a1.y) * inv;
            a0.z = (a0.z + a1.z) * inv; a0.w = (a0.w + a1.w) * inv;
        }
        *(float4*)&ms[nl][lane * 4] = a0;
    }
    __syncthreads();

    // Phase 2: (ms @ Wg) — thread (nt=w, ct=lane) owns 8 nodes x 4 cols
    int ct = lane;
    int nt = w;
    int colb = ct * 4;

    u64 acc2[8][2];
#pragma unroll
    for (int i = 0; i < 8; i++) { acc2[i][0] = 0ull; acc2[i][1] = 0ull; }

    const float4* W4 = (const float4*)Wg;
#pragma unroll 4
    for (int k = 0; k < HIDDEN; k++) {
        float4 wv = W4[k * 32 + ct];
        u64 wp0 = pack2(wv.x, wv.y);
        u64 wp1 = pack2(wv.z, wv.w);
#pragma unroll
        for (int i = 0; i < 8; i++) {
            float m = ms[nt * 8 + i][k];
            u64 mp = pack2(m, m);
            fma2(acc2[i][0], mp, wp0);
            fma2(acc2[i][1], mp, wp1);
        }
    }

    float4 bv = ((const float4*)bg)[ct];
    float4 cs = make_float4(0.f, 0.f, 0.f, 0.f);
#pragma unroll
    for (int i = 0; i < 8; i++) {
        int node = node0 + nt * 8 + i;
        if (node < N_NODES) {
            float4 hv = *(const float4*)(hin + (size_t)node * HIDDEN + colb);
            float lo, hi;
            float4 r;
            unpack2(acc2[i][0], lo, hi);
            r.x = fmaxf(hv.x + lo + bv.x, 0.0f);
            r.y = fmaxf(hv.y + hi + bv.y, 0.0f);
            unpack2(acc2[i][1], lo, hi);
            r.z = fmaxf(hv.z + lo + bv.z, 0.0f);
            r.w = fmaxf(hv.w + hi + bv.w, 0.0f);
            *(float4*)(hout + (size_t)node * HIDDEN + colb) = r;
            cs.x += r.x; cs.y += r.y; cs.z += r.z; cs.w += r.w;
        }
    }
    if (do_reduce) {
        atomicAdd(&d_gsum[colb + 0], cs.x);
        atomicAdd(&d_gsum[colb + 1], cs.y);
        atomicAdd(&d_gsum[colb + 2], cs.z);
        atomicAdd(&d_gsum[colb + 3], cs.w);
    }
}

// ---------------------------------------------------------------------------
__global__ void mlp_kernel(const float* __restrict__ W1,
                           const float* __restrict__ b1,
                           const float* __restrict__ W2,
                           const float* __restrict__ b2,
                           float* __restrict__ out) {
    __shared__ float gs[HIDDEN];
    __shared__ float ts[HIDDEN];
    int t = threadIdx.x;  // 256
    if (t < HIDDEN) gs[t] = d_gsum[t] * (1.0f / (float)N_NODES);
    __syncthreads();
    if (t < HIDDEN) {
        float a = b1[t];
#pragma unroll 8
        for (int k = 0; k < HIDDEN; k++) a += gs[k] * W1[k * HIDDEN + t];
        ts[t] = fmaxf(a, 0.0f);
    }
    __syncthreads();
    {
        float a = b2[t];
#pragma unroll 8
        for (int k = 0; k < HIDDEN; k++) a += ts[k] * W2[k * OUT_DIM + t];
        out[t] = a;
    }
}

// ---------------------------------------------------------------------------
extern "C" void kernel_launch(void* const* d_in, const int* in_sizes, int n_in,
                              void* d_out, int out_size) {
    const float* x   = (const float*)d_in[0];
    const int*   src = (const int*)d_in[1];
    const int*   dst = (const int*)d_in[2];
    const float* Wp  = (const float*)d_in[3];
    const float* bp  = (const float*)d_in[4];
    const float* Wg  = (const float*)d_in[5];
    const float* bg  = (const float*)d_in[6];
    const float* W1  = (const float*)d_in[7];
    const float* b1  = (const float*)d_in[8];
    const float* W2  = (const float*)d_in[9];
    const float* b2  = (const float*)d_in[10];
    float* out = (float*)d_out;

    float *h0, *h1;
    cudaGetSymbolAddress((void**)&h0, d_hbuf0);
    cudaGetSymbolAddress((void**)&h1, d_hbuf1);

    // launch 0: projection (independent of CSR)
    proj_kernel<<<(N_NODES + 31) / 32, 128>>>(x, Wp, bp);
    // launch 1: degree histogram
    hist_kernel<<<(N_EDGES + 255) / 256, 256>>>(dst);
    // launch 2: cooperative scan + fill (also resets cnt + gsum)
    build_kernel<<<BUILD_BLOCKS, 256>>>(src, dst);

    // launches 3..5: GNN layers (ping-pong); last fuses the column reduce
    const int nblocks = (N_NODES + 31) / 32;
    float* bufs[2] = {h0, h1};
    for (int l = 0; l < N_LAYERS; l++) {
        float* hin  = bufs[l & 1];
        float* hout = bufs[(l + 1) & 1];
        layer_kernel<<<nblocks, 128>>>(hin, hout,
                                       Wg + (size_t)l * HIDDEN * HIDDEN,
                                       bg + (size_t)l * HIDDEN,
                                       (l == N_LAYERS - 1) ? 1 : 0);
    }

    // launch 6: MLP head
    mlp_kernel<<<1, 256>>>(W1, b1, W2, b2, out);
}